// round 3
// baseline (speedup 1.0000x reference)
#include <cuda_runtime.h>
#include <cstdint>

// ---------- fast-but-accurate activations (ex2 + rcp, ~1e-6 rel err) ----------
__device__ __forceinline__ float sig_(float x) {
    float e;
    asm("ex2.approx.f32 %0, %1;" : "=f"(e) : "f"(x * -1.4426950408889634f));
    float r;
    asm("rcp.approx.f32 %0, %1;" : "=f"(r) : "f"(e + 1.0f));
    return r;
}
__device__ __forceinline__ float tanh_(float x) {
    return fmaf(2.0f, sig_(2.0f * x), -1.0f);
}

#define TT 14
#define HH 7
#define FF 12
#define NTHR 128

__global__ __launch_bounds__(NTHR, 5)
void lstm_fused_kernel(
    const float* __restrict__ x,
    const float* __restrict__ w1,  const float* __restrict__ b1,
    const float* __restrict__ wih0, const float* __restrict__ whh0,
    const float* __restrict__ bih0, const float* __restrict__ bhh0,
    const float* __restrict__ wih1, const float* __restrict__ whh1,
    const float* __restrict__ bih1, const float* __restrict__ bhh1,
    const float* __restrict__ w2,  const float* __restrict__ b2,
    float* __restrict__ out, int B)
{
    // layer0 row r=(g*7+j), 12 floats: [wih0[r], b0[r], whh0[r][0..6], pad,pad,pad]
    __shared__ __align__(16) float s_l0[28 * 12];
    // layer1 row r, 16 floats: [b1[r], wih1[r][0..6], whh1[r][0..6], pad]
    __shared__ __align__(16) float s_l1[28 * 16];
    __shared__ __align__(16) float s_w1[12];
    __shared__ float s_w2[2 * HH];
    __shared__ float s_b1lin, s_b2;
    // u staged per (local batch, t); 15 stride => conflict-free phase2 reads
    __shared__ float s_u[NTHR * 15];

    const int tid = threadIdx.x;

    for (int r = tid; r < 28; r += NTHR) {
        s_l0[r * 12 + 0] = wih0[r];
        s_l0[r * 12 + 1] = bih0[r] + bhh0[r];
#pragma unroll
        for (int k = 0; k < 7; k++) s_l0[r * 12 + 2 + k] = whh0[r * 7 + k];
        s_l0[r * 12 + 9] = 0.f; s_l0[r * 12 + 10] = 0.f; s_l0[r * 12 + 11] = 0.f;

        s_l1[r * 16 + 0] = bih1[r] + bhh1[r];
#pragma unroll
        for (int k = 0; k < 7; k++) s_l1[r * 16 + 1 + k] = wih1[r * 7 + k];
#pragma unroll
        for (int k = 0; k < 7; k++) s_l1[r * 16 + 8 + k] = whh1[r * 7 + k];
        s_l1[r * 16 + 15] = 0.f;
    }
    if (tid < 2 * HH) s_w2[tid] = w2[tid];
    if (tid < FF)     s_w1[tid] = w1[tid];
    if (tid == 0) { s_b1lin = b1[0]; s_b2 = b2[0]; }
    __syncthreads();

    const int blk_base = blockIdx.x * NTHR;       // first batch element of block
    const int nb = min(NTHR, B - blk_base);       // batches handled by this block
    const int cnt = nb * TT;

    // ---- phase 1: coalesced. idx = bl*TT + t -> contiguous 48B per lane ----
    {
        const float blin = s_b1lin;
        float4 wA = *(const float4*)&s_w1[0];
        float4 wB = *(const float4*)&s_w1[4];
        float4 wC = *(const float4*)&s_w1[8];
        const float* xb = x + (long)blk_base * TT * FF;
#pragma unroll 1
        for (int it = 0; it < TT; it++) {
            int idx = it * NTHR + tid;
            if (idx < cnt) {
                int bl = idx / TT;
                int t  = idx - bl * TT;
                const float4* px = (const float4*)(xb + (long)idx * FF);
                float4 a0 = px[0], a1 = px[1], a2 = px[2];
                float s = blin;
                s = fmaf(a0.x, wA.x, s); s = fmaf(a0.y, wA.y, s);
                s = fmaf(a0.z, wA.z, s); s = fmaf(a0.w, wA.w, s);
                s = fmaf(a1.x, wB.x, s); s = fmaf(a1.y, wB.y, s);
                s = fmaf(a1.z, wB.z, s); s = fmaf(a1.w, wB.w, s);
                s = fmaf(a2.x, wC.x, s); s = fmaf(a2.y, wC.y, s);
                s = fmaf(a2.z, wC.z, s); s = fmaf(a2.w, wC.w, s);
                s_u[bl * 15 + t] = tanh_(s);
            }
        }
    }
    __syncthreads();

    const int b = blk_base + tid;
    if (b >= B) return;

    // ---- phase 2: two stacked LSTM layers, interleaved per time step ----
    float h0[HH], c0[HH], h1[HH], c1[HH];
#pragma unroll
    for (int j = 0; j < HH; j++) { h0[j] = 0.f; c0[j] = 0.f; h1[j] = 0.f; c1[j] = 0.f; }

#pragma unroll 1
    for (int t = 0; t < TT; t++) {
        const float xin = s_u[tid * 15 + t];

        // layer 0
        float hn[HH];
#pragma unroll
        for (int j = 0; j < HH; j++) {
            float z[4];
#pragma unroll
            for (int g = 0; g < 4; g++) {
                const float4* rp = (const float4*)&s_l0[(g * HH + j) * 12];
                float4 r0 = rp[0], r1 = rp[1], r2 = rp[2];
                float zz = fmaf(xin, r0.x, r0.y);
                zz = fmaf(h0[0], r0.z, zz);
                zz = fmaf(h0[1], r0.w, zz);
                zz = fmaf(h0[2], r1.x, zz);
                zz = fmaf(h0[3], r1.y, zz);
                zz = fmaf(h0[4], r1.z, zz);
                zz = fmaf(h0[5], r1.w, zz);
                zz = fmaf(h0[6], r2.x, zz);
                z[g] = zz;
            }
            float cv = fmaf(sig_(z[1]), c0[j], sig_(z[0]) * tanh_(z[2]));
            c0[j] = cv;
            hn[j] = sig_(z[3]) * tanh_(cv);
        }

        // layer 1 (input = hn)
        float hn1[HH];
#pragma unroll
        for (int j = 0; j < HH; j++) {
            float z[4];
#pragma unroll
            for (int g = 0; g < 4; g++) {
                const float4* rp = (const float4*)&s_l1[(g * HH + j) * 16];
                float4 r0 = rp[0], r1 = rp[1], r2 = rp[2], r3 = rp[3];
                float zz = r0.x;
                zz = fmaf(hn[0], r0.y, zz);
                zz = fmaf(hn[1], r0.z, zz);
                zz = fmaf(hn[2], r0.w, zz);
                zz = fmaf(hn[3], r1.x, zz);
                zz = fmaf(hn[4], r1.y, zz);
                zz = fmaf(hn[5], r1.z, zz);
                zz = fmaf(hn[6], r1.w, zz);
                zz = fmaf(h1[0], r2.x, zz);
                zz = fmaf(h1[1], r2.y, zz);
                zz = fmaf(h1[2], r2.z, zz);
                zz = fmaf(h1[3], r2.w, zz);
                zz = fmaf(h1[4], r3.x, zz);
                zz = fmaf(h1[5], r3.y, zz);
                zz = fmaf(h1[6], r3.z, zz);
                z[g] = zz;
            }
            float cv = fmaf(sig_(z[1]), c1[j], sig_(z[0]) * tanh_(z[2]));
            c1[j] = cv;
            hn1[j] = sig_(z[3]) * tanh_(cv);
        }

#pragma unroll
        for (int j = 0; j < HH; j++) { h0[j] = hn[j]; h1[j] = hn1[j]; }
    }

    // ---- phase 3 ----
    float acc = s_b2;
#pragma unroll
    for (int j = 0; j < HH; j++) {
        acc = fmaf(h0[j], s_w2[j], acc);
        acc = fmaf(h1[j], s_w2[HH + j], acc);
    }
    out[b] = acc;
}

extern "C" void kernel_launch(void* const* d_in, const int* in_sizes, int n_in,
                              void* d_out, int out_size) {
    const float* x    = (const float*)d_in[0];
    const float* w1   = (const float*)d_in[1];
    const float* b1   = (const float*)d_in[2];
    const float* wih0 = (const float*)d_in[3];
    const float* whh0 = (const float*)d_in[4];
    const float* bih0 = (const float*)d_in[5];
    const float* bhh0 = (const float*)d_in[6];
    const float* wih1 = (const float*)d_in[7];
    const float* whh1 = (const float*)d_in[8];
    const float* bih1 = (const float*)d_in[9];
    const float* bhh1 = (const float*)d_in[10];
    const float* w2   = (const float*)d_in[11];
    const float* b2   = (const float*)d_in[12];
    float* out = (float*)d_out;

    const int B    = out_size;       // 262144
    const int grid = (B + NTHR - 1) / NTHR;

    lstm_fused_kernel<<<grid, NTHR>>>(x, w1, b1, wih0, whh0, bih0, bhh0,
                                      wih1, whh1, bih1, bhh1, w2, b2,
                                      out, B);
}

// round 4
// speedup vs baseline: 2.2665x; 2.2665x over previous
#include <cuda_runtime.h>
#include <cstdint>

// ---------- fast-but-accurate activations (ex2 + rcp, ~1e-6 rel err) ----------
__device__ __forceinline__ float sig_(float x) {
    float e;
    asm("ex2.approx.f32 %0, %1;" : "=f"(e) : "f"(x * -1.4426950408889634f));
    float r;
    asm("rcp.approx.f32 %0, %1;" : "=f"(r) : "f"(e + 1.0f));
    return r;
}
__device__ __forceinline__ float tanh_(float x) {
    return fmaf(2.0f, sig_(2.0f * x), -1.0f);
}

#define TT 14
#define HH 7
#define FF 12
#define NTHR 128
#define CHUNK 7   // t-steps per layer pass (2 chunks total)

__global__ __launch_bounds__(NTHR)
void lstm_fused_kernel(
    const float* __restrict__ x,
    const float* __restrict__ w1,  const float* __restrict__ b1,
    const float* __restrict__ wih0, const float* __restrict__ whh0,
    const float* __restrict__ bih0, const float* __restrict__ bhh0,
    const float* __restrict__ wih1, const float* __restrict__ whh1,
    const float* __restrict__ bih1, const float* __restrict__ bhh1,
    const float* __restrict__ w2,  const float* __restrict__ b2,
    float* __restrict__ out, int B)
{
    // layer0 row r=(g*7+j), 12 floats: [wih0[r], b0[r], whh0[r][0..6], pad x3]
    __shared__ __align__(16) float s_l0[28 * 12];
    // layer1 row r, 16 floats: [b1[r], wih1[r][0..6], whh1[r][0..6], pad]
    __shared__ __align__(16) float s_l1[28 * 16];
    __shared__ __align__(16) float s_w1[12];
    __shared__ float s_w2[2 * HH];
    __shared__ float s_b1lin, s_b2;
    // tanh(linear1) per (thread, t); stride 15 (odd) => conflict-free
    __shared__ float s_u[NTHR * 15];
    // layer0 hidden stream for current chunk; stride 7 (odd) => conflict-free
    __shared__ float s_h[CHUNK * NTHR * HH];

    const int tid = threadIdx.x;

    for (int r = tid; r < 28; r += NTHR) {
        s_l0[r * 12 + 0] = wih0[r];
        s_l0[r * 12 + 1] = bih0[r] + bhh0[r];
#pragma unroll
        for (int k = 0; k < 7; k++) s_l0[r * 12 + 2 + k] = whh0[r * 7 + k];
        s_l0[r * 12 + 9] = 0.f; s_l0[r * 12 + 10] = 0.f; s_l0[r * 12 + 11] = 0.f;

        s_l1[r * 16 + 0] = bih1[r] + bhh1[r];
#pragma unroll
        for (int k = 0; k < 7; k++) s_l1[r * 16 + 1 + k] = wih1[r * 7 + k];
#pragma unroll
        for (int k = 0; k < 7; k++) s_l1[r * 16 + 8 + k] = whh1[r * 7 + k];
        s_l1[r * 16 + 15] = 0.f;
    }
    if (tid < 2 * HH) s_w2[tid] = w2[tid];
    if (tid < FF)     s_w1[tid] = w1[tid];
    if (tid == 0) { s_b1lin = b1[0]; s_b2 = b2[0]; }
    __syncthreads();

    const int blk_base = blockIdx.x * NTHR;
    const int nb = min(NTHR, B - blk_base);
    const int cnt = nb * TT;

    // ---- phase 1: coalesced linear1 + tanh ----
    {
        const float blin = s_b1lin;
        float4 wA = *(const float4*)&s_w1[0];
        float4 wB = *(const float4*)&s_w1[4];
        float4 wC = *(const float4*)&s_w1[8];
        const float* xb = x + (long)blk_base * TT * FF;
#pragma unroll 1
        for (int it = 0; it < TT; it++) {
            int idx = it * NTHR + tid;
            if (idx < cnt) {
                int bl = idx / TT;
                int t  = idx - bl * TT;
                const float4* px = (const float4*)(xb + (long)idx * FF);
                float4 a0 = px[0], a1 = px[1], a2 = px[2];
                float s = blin;
                s = fmaf(a0.x, wA.x, s); s = fmaf(a0.y, wA.y, s);
                s = fmaf(a0.z, wA.z, s); s = fmaf(a0.w, wA.w, s);
                s = fmaf(a1.x, wB.x, s); s = fmaf(a1.y, wB.y, s);
                s = fmaf(a1.z, wB.z, s); s = fmaf(a1.w, wB.w, s);
                s = fmaf(a2.x, wC.x, s); s = fmaf(a2.y, wC.y, s);
                s = fmaf(a2.z, wC.z, s); s = fmaf(a2.w, wC.w, s);
                s_u[bl * 15 + t] = tanh_(s);
            }
        }
    }
    __syncthreads();

    const int b = blk_base + tid;
    if (b >= B) return;

    // ---- phase 2: layer passes chunked over time ----
    float h0[HH], c0[HH], h1[HH], c1[HH];
#pragma unroll
    for (int j = 0; j < HH; j++) { h0[j] = 0.f; c0[j] = 0.f; h1[j] = 0.f; c1[j] = 0.f; }

#pragma unroll 1
    for (int ch = 0; ch < TT / CHUNK; ch++) {
        // --- layer 0 over this chunk; emit hidden stream to SMEM scratch ---
#pragma unroll 1
        for (int tl = 0; tl < CHUNK; tl++) {
            const float xin = s_u[tid * 15 + (ch * CHUNK + tl)];
            float hn[HH];
#pragma unroll
            for (int j = 0; j < HH; j++) {
                float z[4];
#pragma unroll
                for (int g = 0; g < 4; g++) {
                    const float4* rp = (const float4*)&s_l0[(g * HH + j) * 12];
                    float4 r0 = rp[0], r1 = rp[1], r2 = rp[2];
                    float zz = fmaf(xin, r0.x, r0.y);
                    zz = fmaf(h0[0], r0.z, zz);
                    zz = fmaf(h0[1], r0.w, zz);
                    zz = fmaf(h0[2], r1.x, zz);
                    zz = fmaf(h0[3], r1.y, zz);
                    zz = fmaf(h0[4], r1.z, zz);
                    zz = fmaf(h0[5], r1.w, zz);
                    zz = fmaf(h0[6], r2.x, zz);
                    z[g] = zz;
                }
                float cv = fmaf(sig_(z[1]), c0[j], sig_(z[0]) * tanh_(z[2]));
                c0[j] = cv;
                hn[j] = sig_(z[3]) * tanh_(cv);
            }
            float* hs = &s_h[(tl * NTHR + tid) * HH];
#pragma unroll
            for (int j = 0; j < HH; j++) { hs[j] = hn[j]; h0[j] = hn[j]; }
        }

        // --- layer 1 over this chunk; input = staged layer-0 hidden ---
#pragma unroll 1
        for (int tl = 0; tl < CHUNK; tl++) {
            const float* hs = &s_h[(tl * NTHR + tid) * HH];
            float xin[HH];
#pragma unroll
            for (int k = 0; k < HH; k++) xin[k] = hs[k];

            float hn1[HH];
#pragma unroll
            for (int j = 0; j < HH; j++) {
                float z[4];
#pragma unroll
                for (int g = 0; g < 4; g++) {
                    const float4* rp = (const float4*)&s_l1[(g * HH + j) * 16];
                    float4 r0 = rp[0], r1 = rp[1], r2 = rp[2], r3 = rp[3];
                    float zz = r0.x;
                    zz = fmaf(xin[0], r0.y, zz);
                    zz = fmaf(xin[1], r0.z, zz);
                    zz = fmaf(xin[2], r0.w, zz);
                    zz = fmaf(xin[3], r1.x, zz);
                    zz = fmaf(xin[4], r1.y, zz);
                    zz = fmaf(xin[5], r1.z, zz);
                    zz = fmaf(xin[6], r1.w, zz);
                    zz = fmaf(h1[0], r2.x, zz);
                    zz = fmaf(h1[1], r2.y, zz);
                    zz = fmaf(h1[2], r2.z, zz);
                    zz = fmaf(h1[3], r2.w, zz);
                    zz = fmaf(h1[4], r3.x, zz);
                    zz = fmaf(h1[5], r3.y, zz);
                    zz = fmaf(h1[6], r3.z, zz);
                    z[g] = zz;
                }
                float cv = fmaf(sig_(z[1]), c1[j], sig_(z[0]) * tanh_(z[2]));
                c1[j] = cv;
                hn1[j] = sig_(z[3]) * tanh_(cv);
            }
#pragma unroll
            for (int j = 0; j < HH; j++) h1[j] = hn1[j];
        }
    }

    // ---- phase 3 ----
    float acc = s_b2;
#pragma unroll
    for (int j = 0; j < HH; j++) {
        acc = fmaf(h0[j], s_w2[j], acc);
        acc = fmaf(h1[j], s_w2[HH + j], acc);
    }
    out[b] = acc;
}

extern "C" void kernel_launch(void* const* d_in, const int* in_sizes, int n_in,
                              void* d_out, int out_size) {
    const float* x    = (const float*)d_in[0];
    const float* w1   = (const float*)d_in[1];
    const float* b1   = (const float*)d_in[2];
    const float* wih0 = (const float*)d_in[3];
    const float* whh0 = (const float*)d_in[4];
    const float* bih0 = (const float*)d_in[5];
    const float* bhh0 = (const float*)d_in[6];
    const float* wih1 = (const float*)d_in[7];
    const float* whh1 = (const float*)d_in[8];
    const float* bih1 = (const float*)d_in[9];
    const float* bhh1 = (const float*)d_in[10];
    const float* w2   = (const float*)d_in[11];
    const float* b2   = (const float*)d_in[12];
    float* out = (float*)d_out;

    const int B    = out_size;       // 262144
    const int grid = (B + NTHR - 1) / NTHR;

    lstm_fused_kernel<<<grid, NTHR>>>(x, w1, b1, wih0, whh0, bih0, bhh0,
                                      wih1, whh1, bih1, bhh1, w2, b2,
                                      out, B);
}

// round 5
// speedup vs baseline: 6.7467x; 2.9766x over previous
#include <cuda_runtime.h>
#include <cstdint>

// ---------- fast-but-accurate activations (ex2 + rcp, ~1e-6 rel err) ----------
__device__ __forceinline__ float sig_(float x) {
    float e;
    asm("ex2.approx.f32 %0, %1;" : "=f"(e) : "f"(x * -1.4426950408889634f));
    float r;
    asm("rcp.approx.f32 %0, %1;" : "=f"(r) : "f"(e + 1.0f));
    return r;
}
__device__ __forceinline__ float tanh_(float x) {
    return fmaf(2.0f, sig_(2.0f * x), -1.0f);
}

// volatile LDS.128: uncacheable, unhoistable -> kills ptxas weight-caching
__device__ __forceinline__ float4 lds128v(const float* p) {
    float4 v;
    unsigned saddr = (unsigned)__cvta_generic_to_shared(p);
    asm volatile("ld.volatile.shared.v4.f32 {%0,%1,%2,%3}, [%4];"
                 : "=f"(v.x), "=f"(v.y), "=f"(v.z), "=f"(v.w)
                 : "r"(saddr));
    return v;
}

#define TT 14
#define HH 7
#define FF 12
#define NTHR 128

__global__ __launch_bounds__(NTHR)
void lstm_fused_kernel(
    const float* __restrict__ x,
    const float* __restrict__ w1,  const float* __restrict__ b1,
    const float* __restrict__ wih0, const float* __restrict__ whh0,
    const float* __restrict__ bih0, const float* __restrict__ bhh0,
    const float* __restrict__ wih1, const float* __restrict__ whh1,
    const float* __restrict__ bih1, const float* __restrict__ bhh1,
    const float* __restrict__ w2,  const float* __restrict__ b2,
    float* __restrict__ out, int B)
{
    // layer0 row r=(g*7+j), 12 floats: [wih0[r], b0[r], whh0[r][0..6], pad x3]
    __shared__ __align__(16) float s_l0[28 * 12];
    // layer1 row r, 16 floats: [b1[r], wih1[r][0..6], whh1[r][0..6], pad]
    __shared__ __align__(16) float s_l1[28 * 16];
    __shared__ __align__(16) float s_w1[12];
    __shared__ float s_w2[2 * HH];
    __shared__ float s_b1lin, s_b2;
    // tanh(linear1) per (thread, t); stride 15 (odd) => conflict-free
    __shared__ float s_u[NTHR * 15];

    const int tid = threadIdx.x;

    for (int r = tid; r < 28; r += NTHR) {
        s_l0[r * 12 + 0] = wih0[r];
        s_l0[r * 12 + 1] = bih0[r] + bhh0[r];
#pragma unroll
        for (int k = 0; k < 7; k++) s_l0[r * 12 + 2 + k] = whh0[r * 7 + k];
        s_l0[r * 12 + 9] = 0.f; s_l0[r * 12 + 10] = 0.f; s_l0[r * 12 + 11] = 0.f;

        s_l1[r * 16 + 0] = bih1[r] + bhh1[r];
#pragma unroll
        for (int k = 0; k < 7; k++) s_l1[r * 16 + 1 + k] = wih1[r * 7 + k];
#pragma unroll
        for (int k = 0; k < 7; k++) s_l1[r * 16 + 8 + k] = whh1[r * 7 + k];
        s_l1[r * 16 + 15] = 0.f;
    }
    if (tid < 2 * HH) s_w2[tid] = w2[tid];
    if (tid < FF)     s_w1[tid] = w1[tid];
    if (tid == 0) { s_b1lin = b1[0]; s_b2 = b2[0]; }
    __syncthreads();

    const int blk_base = blockIdx.x * NTHR;
    const int nb = min(NTHR, B - blk_base);
    const int cnt = nb * TT;

    // ---- phase 1: coalesced linear1 + tanh ----
    {
        const float blin = s_b1lin;
        float4 wA = *(const float4*)&s_w1[0];
        float4 wB = *(const float4*)&s_w1[4];
        float4 wC = *(const float4*)&s_w1[8];
        const float* xb = x + (long)blk_base * TT * FF;
#pragma unroll 1
        for (int it = 0; it < TT; it++) {
            int idx = it * NTHR + tid;
            if (idx < cnt) {
                int bl = idx / TT;
                int t  = idx - bl * TT;
                const float4* px = (const float4*)(xb + (long)idx * FF);
                float4 a0 = px[0], a1 = px[1], a2 = px[2];
                float s = blin;
                s = fmaf(a0.x, wA.x, s); s = fmaf(a0.y, wA.y, s);
                s = fmaf(a0.z, wA.z, s); s = fmaf(a0.w, wA.w, s);
                s = fmaf(a1.x, wB.x, s); s = fmaf(a1.y, wB.y, s);
                s = fmaf(a1.z, wB.z, s); s = fmaf(a1.w, wB.w, s);
                s = fmaf(a2.x, wC.x, s); s = fmaf(a2.y, wC.y, s);
                s = fmaf(a2.z, wC.z, s); s = fmaf(a2.w, wC.w, s);
                s_u[bl * 15 + t] = tanh_(s);
            }
        }
    }
    __syncthreads();

    const int b = blk_base + tid;
    if (b >= B) return;

    // ---- phase 2: two stacked LSTM layers, interleaved per time step ----
    float h0[HH], c0[HH], h1[HH], c1[HH];
#pragma unroll
    for (int j = 0; j < HH; j++) { h0[j] = 0.f; c0[j] = 0.f; h1[j] = 0.f; c1[j] = 0.f; }

#pragma unroll 1
    for (int t = 0; t < TT; t++) {
        const float xin = s_u[tid * 15 + t];

        // layer 0
        float hn[HH];
#pragma unroll
        for (int j = 0; j < HH; j++) {
            float z[4];
#pragma unroll
            for (int g = 0; g < 4; g++) {
                const float* rp = &s_l0[(g * HH + j) * 12];
                float4 r0 = lds128v(rp);
                float4 r1 = lds128v(rp + 4);
                float  r2 = s_l0[(g * HH + j) * 12 + 8];  // lone scalar (volatile not needed; cheap)
                float zz = fmaf(xin, r0.x, r0.y);
                zz = fmaf(h0[0], r0.z, zz);
                zz = fmaf(h0[1], r0.w, zz);
                zz = fmaf(h0[2], r1.x, zz);
                zz = fmaf(h0[3], r1.y, zz);
                zz = fmaf(h0[4], r1.z, zz);
                zz = fmaf(h0[5], r1.w, zz);
                zz = fmaf(h0[6], r2, zz);
                z[g] = zz;
            }
            float cv = fmaf(sig_(z[1]), c0[j], sig_(z[0]) * tanh_(z[2]));
            c0[j] = cv;
            hn[j] = sig_(z[3]) * tanh_(cv);
        }

        // layer 1 (input = hn)
        float hn1[HH];
#pragma unroll
        for (int j = 0; j < HH; j++) {
            float z[4];
#pragma unroll
            for (int g = 0; g < 4; g++) {
                const float* rp = &s_l1[(g * HH + j) * 16];
                float4 r0 = lds128v(rp);
                float4 r1 = lds128v(rp + 4);
                float4 r2 = lds128v(rp + 8);
                float4 r3 = lds128v(rp + 12);
                float zz = r0.x;
                zz = fmaf(hn[0], r0.y, zz);
                zz = fmaf(hn[1], r0.z, zz);
                zz = fmaf(hn[2], r0.w, zz);
                zz = fmaf(hn[3], r1.x, zz);
                zz = fmaf(hn[4], r1.y, zz);
                zz = fmaf(hn[5], r1.z, zz);
                zz = fmaf(hn[6], r1.w, zz);
                zz = fmaf(h1[0], r2.x, zz);
                zz = fmaf(h1[1], r2.y, zz);
                zz = fmaf(h1[2], r2.z, zz);
                zz = fmaf(h1[3], r2.w, zz);
                zz = fmaf(h1[4], r3.x, zz);
                zz = fmaf(h1[5], r3.y, zz);
                zz = fmaf(h1[6], r3.z, zz);
                z[g] = zz;
            }
            float cv = fmaf(sig_(z[1]), c1[j], sig_(z[0]) * tanh_(z[2]));
            c1[j] = cv;
            hn1[j] = sig_(z[3]) * tanh_(cv);
        }

#pragma unroll
        for (int j = 0; j < HH; j++) { h0[j] = hn[j]; h1[j] = hn1[j]; }
    }

    // ---- phase 3 ----
    float acc = s_b2;
#pragma unroll
    for (int j = 0; j < HH; j++) {
        acc = fmaf(h0[j], s_w2[j], acc);
        acc = fmaf(h1[j], s_w2[HH + j], acc);
    }
    out[b] = acc;
}

extern "C" void kernel_launch(void* const* d_in, const int* in_sizes, int n_in,
                              void* d_out, int out_size) {
    const float* x    = (const float*)d_in[0];
    const float* w1   = (const float*)d_in[1];
    const float* b1   = (const float*)d_in[2];
    const float* wih0 = (const float*)d_in[3];
    const float* whh0 = (const float*)d_in[4];
    const float* bih0 = (const float*)d_in[5];
    const float* bhh0 = (const float*)d_in[6];
    const float* wih1 = (const float*)d_in[7];
    const float* whh1 = (const float*)d_in[8];
    const float* bih1 = (const float*)d_in[9];
    const float* bhh1 = (const float*)d_in[10];
    const float* w2   = (const float*)d_in[11];
    const float* b2   = (const float*)d_in[12];
    float* out = (float*)d_out;

    const int B    = out_size;       // 262144
    const int grid = (B + NTHR - 1) / NTHR;

    lstm_fused_kernel<<<grid, NTHR>>>(x, w1, b1, wih0, whh0, bih0, bhh0,
                                      wih1, whh1, bih1, bhh1, w2, b2,
                                      out, B);
}

// round 6
// speedup vs baseline: 8.3038x; 1.2308x over previous
#include <cuda_runtime.h>
#include <cstdint>

// ---------- hardware tanh (1 MUFU op); sigmoid via tanh identity ----------
__device__ __forceinline__ float tanh_(float x) {
    float r;
    asm("tanh.approx.f32 %0, %1;" : "=f"(r) : "f"(x));
    return r;
}
__device__ __forceinline__ float sig_(float x) {
    // sigmoid(x) = 0.5*tanh(x/2) + 0.5
    return fmaf(0.5f, tanh_(0.5f * x), 0.5f);
}

// volatile LDS.128: uncacheable, unhoistable -> kills ptxas weight-caching
__device__ __forceinline__ float4 lds128v(const float* p) {
    float4 v;
    unsigned saddr = (unsigned)__cvta_generic_to_shared(p);
    asm volatile("ld.volatile.shared.v4.f32 {%0,%1,%2,%3}, [%4];"
                 : "=f"(v.x), "=f"(v.y), "=f"(v.z), "=f"(v.w)
                 : "r"(saddr));
    return v;
}

#define TT 14
#define HH 7
#define FF 12
#define NTHR 128

__global__ __launch_bounds__(NTHR)
void lstm_fused_kernel(
    const float* __restrict__ x,
    const float* __restrict__ w1,  const float* __restrict__ b1,
    const float* __restrict__ wih0, const float* __restrict__ whh0,
    const float* __restrict__ bih0, const float* __restrict__ bhh0,
    const float* __restrict__ wih1, const float* __restrict__ whh1,
    const float* __restrict__ bih1, const float* __restrict__ bhh1,
    const float* __restrict__ w2,  const float* __restrict__ b2,
    float* __restrict__ out, int B)
{
    // layer0 row r=(g*7+j), 12 floats: [wih0[r], b0[r], whh0[r][0..6], pad x3]
    __shared__ __align__(16) float s_l0[28 * 12];
    // layer1 row r, 16 floats: [b1[r], wih1[r][0..6], whh1[r][0..6], pad]
    __shared__ __align__(16) float s_l1[28 * 16];
    __shared__ __align__(16) float s_w1[12];
    __shared__ float s_w2[2 * HH];
    __shared__ float s_b1lin, s_b2;
    // tanh(linear1) per (thread, t); stride 15 (odd) => conflict-free
    __shared__ float s_u[NTHR * 15];

    const int tid = threadIdx.x;

    for (int r = tid; r < 28; r += NTHR) {
        s_l0[r * 12 + 0] = wih0[r];
        s_l0[r * 12 + 1] = bih0[r] + bhh0[r];
#pragma unroll
        for (int k = 0; k < 7; k++) s_l0[r * 12 + 2 + k] = whh0[r * 7 + k];
        s_l0[r * 12 + 9] = 0.f; s_l0[r * 12 + 10] = 0.f; s_l0[r * 12 + 11] = 0.f;

        s_l1[r * 16 + 0] = bih1[r] + bhh1[r];
#pragma unroll
        for (int k = 0; k < 7; k++) s_l1[r * 16 + 1 + k] = wih1[r * 7 + k];
#pragma unroll
        for (int k = 0; k < 7; k++) s_l1[r * 16 + 8 + k] = whh1[r * 7 + k];
        s_l1[r * 16 + 15] = 0.f;
    }
    if (tid < 2 * HH) s_w2[tid] = w2[tid];
    if (tid < FF)     s_w1[tid] = w1[tid];
    if (tid == 0) { s_b1lin = b1[0]; s_b2 = b2[0]; }
    __syncthreads();

    const int blk_base = blockIdx.x * NTHR;
    const int nb = min(NTHR, B - blk_base);
    const int cnt = nb * TT;

    // ---- phase 1: coalesced linear1 + tanh ----
    {
        const float blin = s_b1lin;
        float4 wA = *(const float4*)&s_w1[0];
        float4 wB = *(const float4*)&s_w1[4];
        float4 wC = *(const float4*)&s_w1[8];
        const float* xb = x + (long)blk_base * TT * FF;
#pragma unroll 1
        for (int it = 0; it < TT; it++) {
            int idx = it * NTHR + tid;
            if (idx < cnt) {
                int bl = idx / TT;
                int t  = idx - bl * TT;
                const float4* px = (const float4*)(xb + (long)idx * FF);
                float4 a0 = px[0], a1 = px[1], a2 = px[2];
                float s = blin;
                s = fmaf(a0.x, wA.x, s); s = fmaf(a0.y, wA.y, s);
                s = fmaf(a0.z, wA.z, s); s = fmaf(a0.w, wA.w, s);
                s = fmaf(a1.x, wB.x, s); s = fmaf(a1.y, wB.y, s);
                s = fmaf(a1.z, wB.z, s); s = fmaf(a1.w, wB.w, s);
                s = fmaf(a2.x, wC.x, s); s = fmaf(a2.y, wC.y, s);
                s = fmaf(a2.z, wC.z, s); s = fmaf(a2.w, wC.w, s);
                s_u[bl * 15 + t] = tanh_(s);
            }
        }
    }
    __syncthreads();

    const int b = blk_base + tid;
    if (b >= B) return;

    // ---- phase 2: two stacked LSTM layers, interleaved per time step ----
    float h0[HH], c0[HH], h1[HH], c1[HH];
#pragma unroll
    for (int j = 0; j < HH; j++) { h0[j] = 0.f; c0[j] = 0.f; h1[j] = 0.f; c1[j] = 0.f; }

#pragma unroll 1
    for (int t = 0; t < TT; t++) {
        const float xin = s_u[tid * 15 + t];

        // layer 0
        float hn[HH];
#pragma unroll
        for (int j = 0; j < HH; j++) {
            float z[4];
#pragma unroll
            for (int g = 0; g < 4; g++) {
                const float* rp = &s_l0[(g * HH + j) * 12];
                float4 r0 = lds128v(rp);
                float4 r1 = lds128v(rp + 4);
                float  r2 = s_l0[(g * HH + j) * 12 + 8];
                float zz = fmaf(xin, r0.x, r0.y);
                zz = fmaf(h0[0], r0.z, zz);
                zz = fmaf(h0[1], r0.w, zz);
                zz = fmaf(h0[2], r1.x, zz);
                zz = fmaf(h0[3], r1.y, zz);
                zz = fmaf(h0[4], r1.z, zz);
                zz = fmaf(h0[5], r1.w, zz);
                zz = fmaf(h0[6], r2, zz);
                z[g] = zz;
            }
            float cv = fmaf(sig_(z[1]), c0[j], sig_(z[0]) * tanh_(z[2]));
            c0[j] = cv;
            hn[j] = sig_(z[3]) * tanh_(cv);
        }

        // layer 1 (input = hn)
        float hn1[HH];
#pragma unroll
        for (int j = 0; j < HH; j++) {
            float z[4];
#pragma unroll
            for (int g = 0; g < 4; g++) {
                const float* rp = &s_l1[(g * HH + j) * 16];
                float4 r0 = lds128v(rp);
                float4 r1 = lds128v(rp + 4);
                float4 r2 = lds128v(rp + 8);
                float4 r3 = lds128v(rp + 12);
                float zz = r0.x;
                zz = fmaf(hn[0], r0.y, zz);
                zz = fmaf(hn[1], r0.z, zz);
                zz = fmaf(hn[2], r0.w, zz);
                zz = fmaf(hn[3], r1.x, zz);
                zz = fmaf(hn[4], r1.y, zz);
                zz = fmaf(hn[5], r1.z, zz);
                zz = fmaf(hn[6], r1.w, zz);
                zz = fmaf(h1[0], r2.x, zz);
                zz = fmaf(h1[1], r2.y, zz);
                zz = fmaf(h1[2], r2.z, zz);
                zz = fmaf(h1[3], r2.w, zz);
                zz = fmaf(h1[4], r3.x, zz);
                zz = fmaf(h1[5], r3.y, zz);
                zz = fmaf(h1[6], r3.z, zz);
                z[g] = zz;
            }
            float cv = fmaf(sig_(z[1]), c1[j], sig_(z[0]) * tanh_(z[2]));
            c1[j] = cv;
            hn1[j] = sig_(z[3]) * tanh_(cv);
        }

#pragma unroll
        for (int j = 0; j < HH; j++) { h0[j] = hn[j]; h1[j] = hn1[j]; }
    }

    // ---- phase 3 ----
    float acc = s_b2;
#pragma unroll
    for (int j = 0; j < HH; j++) {
        acc = fmaf(h0[j], s_w2[j], acc);
        acc = fmaf(h1[j], s_w2[HH + j], acc);
    }
    out[b] = acc;
}

extern "C" void kernel_launch(void* const* d_in, const int* in_sizes, int n_in,
                              void* d_out, int out_size) {
    const float* x    = (const float*)d_in[0];
    const float* w1   = (const float*)d_in[1];
    const float* b1   = (const float*)d_in[2];
    const float* wih0 = (const float*)d_in[3];
    const float* whh0 = (const float*)d_in[4];
    const float* bih0 = (const float*)d_in[5];
    const float* bhh0 = (const float*)d_in[6];
    const float* wih1 = (const float*)d_in[7];
    const float* whh1 = (const float*)d_in[8];
    const float* bih1 = (const float*)d_in[9];
    const float* bhh1 = (const float*)d_in[10];
    const float* w2   = (const float*)d_in[11];
    const float* b2   = (const float*)d_in[12];
    float* out = (float*)d_out;

    const int B    = out_size;       // 262144
    const int grid = (B + NTHR - 1) / NTHR;

    lstm_fused_kernel<<<grid, NTHR>>>(x, w1, b1, wih0, whh0, bih0, bhh0,
                                      wih1, whh1, bih1, bhh1, w2, b2,
                                      out, B);
}

// round 7
// speedup vs baseline: 9.7826x; 1.1781x over previous
#include <cuda_runtime.h>
#include <cstdint>

// ---------- hardware tanh (1 MUFU op); sigmoid via tanh identity ----------
__device__ __forceinline__ float tanh_(float x) {
    float r;
    asm("tanh.approx.f32 %0, %1;" : "=f"(r) : "f"(x));
    return r;
}
__device__ __forceinline__ float sig_(float x) {
    return fmaf(0.5f, tanh_(0.5f * x), 0.5f);
}

// volatile LDS.128: uncacheable, unhoistable -> kills ptxas weight-caching
__device__ __forceinline__ float4 lds128v(const float* p) {
    float4 v;
    unsigned saddr = (unsigned)__cvta_generic_to_shared(p);
    asm volatile("ld.volatile.shared.v4.f32 {%0,%1,%2,%3}, [%4];"
                 : "=f"(v.x), "=f"(v.y), "=f"(v.z), "=f"(v.w)
                 : "r"(saddr));
    return v;
}

#define TT 14
#define HH 7
#define FF 12
#define NTHR 128
#define EB 2            // batch elements per thread
#define BPB (NTHR * EB) // batch elements per block = 256

__global__ __launch_bounds__(NTHR)
void lstm_fused_kernel(
    const float* __restrict__ x,
    const float* __restrict__ w1,  const float* __restrict__ b1,
    const float* __restrict__ wih0, const float* __restrict__ whh0,
    const float* __restrict__ bih0, const float* __restrict__ bhh0,
    const float* __restrict__ wih1, const float* __restrict__ whh1,
    const float* __restrict__ bih1, const float* __restrict__ bhh1,
    const float* __restrict__ w2,  const float* __restrict__ b2,
    float* __restrict__ out, int B)
{
    // layer0 row r=(g*7+j), 12 floats: [wih0[r], b0[r], whh0[r][0..6], pad x3]
    __shared__ __align__(16) float s_l0[28 * 12];
    // layer1 row r, 16 floats: [b1[r], wih1[r][0..6], whh1[r][0..6], pad]
    __shared__ __align__(16) float s_l1[28 * 16];
    __shared__ __align__(16) float s_w1[12];
    __shared__ float s_w2[2 * HH];
    __shared__ float s_b1lin, s_b2;
    // tanh(linear1) per (local batch, t); stride 15 (odd) => conflict-free
    __shared__ float s_u[BPB * 15];

    const int tid = threadIdx.x;

    for (int r = tid; r < 28; r += NTHR) {
        s_l0[r * 12 + 0] = wih0[r];
        s_l0[r * 12 + 1] = bih0[r] + bhh0[r];
#pragma unroll
        for (int k = 0; k < 7; k++) s_l0[r * 12 + 2 + k] = whh0[r * 7 + k];
        s_l0[r * 12 + 9] = 0.f; s_l0[r * 12 + 10] = 0.f; s_l0[r * 12 + 11] = 0.f;

        s_l1[r * 16 + 0] = bih1[r] + bhh1[r];
#pragma unroll
        for (int k = 0; k < 7; k++) s_l1[r * 16 + 1 + k] = wih1[r * 7 + k];
#pragma unroll
        for (int k = 0; k < 7; k++) s_l1[r * 16 + 8 + k] = whh1[r * 7 + k];
        s_l1[r * 16 + 15] = 0.f;
    }
    if (tid < 2 * HH) s_w2[tid] = w2[tid];
    if (tid < FF)     s_w1[tid] = w1[tid];
    if (tid == 0) { s_b1lin = b1[0]; s_b2 = b2[0]; }
    __syncthreads();

    const int blk_base = blockIdx.x * BPB;
    const int nb = min(BPB, B - blk_base);
    const int cnt = nb * TT;

    // ---- phase 1: coalesced linear1 + tanh over 256 local elements ----
    {
        const float blin = s_b1lin;
        float4 wA = *(const float4*)&s_w1[0];
        float4 wB = *(const float4*)&s_w1[4];
        float4 wC = *(const float4*)&s_w1[8];
        const float* xb = x + (long)blk_base * TT * FF;
#pragma unroll 1
        for (int it = 0; it < EB * TT; it++) {
            int idx = it * NTHR + tid;
            if (idx < cnt) {
                int bl = idx / TT;
                int t  = idx - bl * TT;
                const float4* px = (const float4*)(xb + (long)idx * FF);
                float4 a0 = px[0], a1 = px[1], a2 = px[2];
                float s = blin;
                s = fmaf(a0.x, wA.x, s); s = fmaf(a0.y, wA.y, s);
                s = fmaf(a0.z, wA.z, s); s = fmaf(a0.w, wA.w, s);
                s = fmaf(a1.x, wB.x, s); s = fmaf(a1.y, wB.y, s);
                s = fmaf(a1.z, wB.z, s); s = fmaf(a1.w, wB.w, s);
                s = fmaf(a2.x, wC.x, s); s = fmaf(a2.y, wC.y, s);
                s = fmaf(a2.z, wC.z, s); s = fmaf(a2.w, wC.w, s);
                s_u[bl * 15 + t] = tanh_(s);
            }
        }
    }
    __syncthreads();

    const int bA = blk_base + tid;
    const int bB = blk_base + NTHR + tid;
    if (bA >= B) return;
    const bool hasB = (bB < B);
    // s_u row index for element B (clamped if absent; value unused then)
    const int uB = hasB ? (NTHR + tid) : tid;

    // ---- phase 2: two stacked LSTM layers x two batch elements ----
    float h0A[HH], c0A[HH], h1A[HH], c1A[HH];
    float h0B[HH], c0B[HH], h1B[HH], c1B[HH];
#pragma unroll
    for (int j = 0; j < HH; j++) {
        h0A[j] = 0.f; c0A[j] = 0.f; h1A[j] = 0.f; c1A[j] = 0.f;
        h0B[j] = 0.f; c0B[j] = 0.f; h1B[j] = 0.f; c1B[j] = 0.f;
    }

#pragma unroll 1
    for (int t = 0; t < TT; t++) {
        const float xinA = s_u[tid * 15 + t];
        const float xinB = s_u[uB * 15 + t];

        // layer 0 (both elements share each weight row load)
        float hnA[HH], hnB[HH];
#pragma unroll
        for (int j = 0; j < HH; j++) {
            float zA[4], zB[4];
#pragma unroll
            for (int g = 0; g < 4; g++) {
                const float* rp = &s_l0[(g * HH + j) * 12];
                float4 r0 = lds128v(rp);
                float4 r1 = lds128v(rp + 4);
                float  r2 = s_l0[(g * HH + j) * 12 + 8];
                float a = fmaf(xinA, r0.x, r0.y);
                float bq = fmaf(xinB, r0.x, r0.y);
                a  = fmaf(h0A[0], r0.z, a);  bq = fmaf(h0B[0], r0.z, bq);
                a  = fmaf(h0A[1], r0.w, a);  bq = fmaf(h0B[1], r0.w, bq);
                a  = fmaf(h0A[2], r1.x, a);  bq = fmaf(h0B[2], r1.x, bq);
                a  = fmaf(h0A[3], r1.y, a);  bq = fmaf(h0B[3], r1.y, bq);
                a  = fmaf(h0A[4], r1.z, a);  bq = fmaf(h0B[4], r1.z, bq);
                a  = fmaf(h0A[5], r1.w, a);  bq = fmaf(h0B[5], r1.w, bq);
                a  = fmaf(h0A[6], r2,   a);  bq = fmaf(h0B[6], r2,   bq);
                zA[g] = a; zB[g] = bq;
            }
            float cvA = fmaf(sig_(zA[1]), c0A[j], sig_(zA[0]) * tanh_(zA[2]));
            float cvB = fmaf(sig_(zB[1]), c0B[j], sig_(zB[0]) * tanh_(zB[2]));
            c0A[j] = cvA; c0B[j] = cvB;
            hnA[j] = sig_(zA[3]) * tanh_(cvA);
            hnB[j] = sig_(zB[3]) * tanh_(cvB);
        }

        // layer 1
        float hn1A[HH], hn1B[HH];
#pragma unroll
        for (int j = 0; j < HH; j++) {
            float zA[4], zB[4];
#pragma unroll
            for (int g = 0; g < 4; g++) {
                const float* rp = &s_l1[(g * HH + j) * 16];
                float4 r0 = lds128v(rp);
                float4 r1 = lds128v(rp + 4);
                float4 r2 = lds128v(rp + 8);
                float4 r3 = lds128v(rp + 12);
                float a = r0.x, bq = r0.x;
                a = fmaf(hnA[0], r0.y, a);  bq = fmaf(hnB[0], r0.y, bq);
                a = fmaf(hnA[1], r0.z, a);  bq = fmaf(hnB[1], r0.z, bq);
                a = fmaf(hnA[2], r0.w, a);  bq = fmaf(hnB[2], r0.w, bq);
                a = fmaf(hnA[3], r1.x, a);  bq = fmaf(hnB[3], r1.x, bq);
                a = fmaf(hnA[4], r1.y, a);  bq = fmaf(hnB[4], r1.y, bq);
                a = fmaf(hnA[5], r1.z, a);  bq = fmaf(hnB[5], r1.z, bq);
                a = fmaf(hnA[6], r1.w, a);  bq = fmaf(hnB[6], r1.w, bq);
                a = fmaf(h1A[0], r2.x, a);  bq = fmaf(h1B[0], r2.x, bq);
                a = fmaf(h1A[1], r2.y, a);  bq = fmaf(h1B[1], r2.y, bq);
                a = fmaf(h1A[2], r2.z, a);  bq = fmaf(h1B[2], r2.z, bq);
                a = fmaf(h1A[3], r2.w, a);  bq = fmaf(h1B[3], r2.w, bq);
                a = fmaf(h1A[4], r3.x, a);  bq = fmaf(h1B[4], r3.x, bq);
                a = fmaf(h1A[5], r3.y, a);  bq = fmaf(h1B[5], r3.y, bq);
                a = fmaf(h1A[6], r3.z, a);  bq = fmaf(h1B[6], r3.z, bq);
                zA[g] = a; zB[g] = bq;
            }
            float cvA = fmaf(sig_(zA[1]), c1A[j], sig_(zA[0]) * tanh_(zA[2]));
            float cvB = fmaf(sig_(zB[1]), c1B[j], sig_(zB[0]) * tanh_(zB[2]));
            c1A[j] = cvA; c1B[j] = cvB;
            hn1A[j] = sig_(zA[3]) * tanh_(cvA);
            hn1B[j] = sig_(zB[3]) * tanh_(cvB);
        }

#pragma unroll
        for (int j = 0; j < HH; j++) {
            h0A[j] = hnA[j]; h1A[j] = hn1A[j];
            h0B[j] = hnB[j]; h1B[j] = hn1B[j];
        }
    }

    // ---- phase 3 ----
    float accA = s_b2, accB = s_b2;
#pragma unroll
    for (int j = 0; j < HH; j++) {
        accA = fmaf(h0A[j], s_w2[j], accA);
        accA = fmaf(h1A[j], s_w2[HH + j], accA);
        accB = fmaf(h0B[j], s_w2[j], accB);
        accB = fmaf(h1B[j], s_w2[HH + j], accB);
    }
    out[bA] = accA;
    if (hasB) out[bB] = accB;
}

extern "C" void kernel_launch(void* const* d_in, const int* in_sizes, int n_in,
                              void* d_out, int out_size) {
    const float* x    = (const float*)d_in[0];
    const float* w1   = (const float*)d_in[1];
    const float* b1   = (const float*)d_in[2];
    const float* wih0 = (const float*)d_in[3];
    const float* whh0 = (const float*)d_in[4];
    const float* bih0 = (const float*)d_in[5];
    const float* bhh0 = (const float*)d_in[6];
    const float* wih1 = (const float*)d_in[7];
    const float* whh1 = (const float*)d_in[8];
    const float* bih1 = (const float*)d_in[9];
    const float* bhh1 = (const float*)d_in[10];
    const float* w2   = (const float*)d_in[11];
    const float* b2   = (const float*)d_in[12];
    float* out = (float*)d_out;

    const int B    = out_size;       // 262144
    const int grid = (B + BPB - 1) / BPB;

    lstm_fused_kernel<<<grid, NTHR>>>(x, w1, b1, wih0, whh0, bih0, bhh0,
                                      wih1, whh1, bih1, bhh1, w2, b2,
                                      out, B);
}